// round 15
// baseline (speedup 1.0000x reference)
#include <cuda_runtime.h>
#include <cstdint>

// SimpleSparseConvNet: rulebook sparse conv, Cin=1, Cout=16.
//  - k_bounds_vec: segment boundaries from sorted k_idx via consecutive int4
//    loads (coalesced linear scan, no atomics, idempotent stores).
//  - k_count: byte histogram of out_idx only (8 strided address-disjoint
//    streams, fire-and-forget RED).
//  - k_zero_multi: zero only deg>=2 output rows (quad-lane coalesced).
//  - k_scatter: segment-lockstep grid (27, Y); k uniform per block (weight
//    hoisted); deg==1 rows STG.128, deg>=2 rows red.v4 (L2-resident lines
//    thanks to lockstep segment progress).

#define MAX_NOUT (4 * 1024 * 1024)
#define NS 4
#define CH (64 * NS)          // entries per block-chunk in scatter
#define NC 8                  // streams in k_count

__device__ __align__(16) unsigned char g_counts[MAX_NOUT];
__device__ unsigned int g_segstart[32];

__device__ __forceinline__ void red_add_v4(float* addr, float a, float b, float c, float d) {
    asm volatile("red.global.add.v4.f32 [%0], {%1, %2, %3, %4};"
                 :: "l"(addr), "f"(a), "f"(b), "f"(c), "f"(d)
                 : "memory");
}

// ---- K0: segment boundaries via vectorized linear scan of k_idx -------------
__global__ void __launch_bounds__(256)
k_bounds_vec(const int* __restrict__ k_idx, int M) {
    int t = blockIdx.x * blockDim.x + threadIdx.x;
    int base = t * 4;
    if (base >= M) return;

    if (base + 3 < M) {
        int4 k = __ldg(reinterpret_cast<const int4*>(k_idx) + t);
        int kprev = (base > 0) ? __ldg(&k_idx[base - 1]) : -1;
        int kv[5] = { kprev, k.x, k.y, k.z, k.w };
#pragma unroll
        for (int r = 0; r < 4; r++) {
            if (kv[r] < kv[r + 1])
                for (int s = kv[r] + 1; s <= kv[r + 1]; s++)
                    g_segstart[s] = (unsigned int)(base + r);
        }
        if (base + 4 == M)
            for (int s = k.w + 1; s <= 27; s++)
                g_segstart[s] = (unsigned int)M;
    } else {
        int kprev = (base > 0) ? __ldg(&k_idx[base - 1]) : -1;
        for (int m = base; m < M; m++) {
            int k = __ldg(&k_idx[m]);
            if (kprev < k)
                for (int s = kprev + 1; s <= k; s++)
                    g_segstart[s] = (unsigned int)m;
            kprev = k;
            if (m == M - 1)
                for (int s = k + 1; s <= 27; s++)
                    g_segstart[s] = (unsigned int)M;
        }
    }
}

// ---- K1: byte histogram of out_idx, 8 strided streams ------------------------
__global__ void __launch_bounds__(256)
k_count(const int* __restrict__ out_idx, int M, int Q) {
    int q = blockIdx.x * blockDim.x + threadIdx.x;
    if (q >= Q) return;

    const int mLast = q + (NC - 1) * Q;
    const bool vLast = (mLast < M);
    int m[NC];
#pragma unroll
    for (int r = 0; r < NC - 1; r++) m[r] = q + r * Q;
    m[NC - 1] = vLast ? mLast : (M - 1);

    int o[NC];
#pragma unroll
    for (int r = 0; r < NC; r++) o[r] = __ldg(&out_idx[m[r]]);

#pragma unroll
    for (int r = 0; r < NC; r++) {
        if (r < NC - 1 || vLast)
            atomicAdd(reinterpret_cast<unsigned int*>(g_counts) + (o[r] >> 2),
                      1u << ((o[r] & 3) * 8));
    }
}

// ---- K2: zero output rows with deg >= 2 (thread per float4, coalesced) ------
__global__ void __launch_bounds__(256)
k_zero_multi(float* __restrict__ out, int n_out) {
    int tid = blockIdx.x * blockDim.x + threadIdx.x;
    int o = tid >> 2;
    if (o >= n_out) return;
    if (__ldg(&g_counts[o]) >= 2)
        reinterpret_cast<float4*>(out)[tid] = make_float4(0.f, 0.f, 0.f, 0.f);
}

// ---- K3: segment-lockstep scatter --------------------------------------------
__global__ void __launch_bounds__(256)
k_scatter(const float* __restrict__ feats,
          const float* __restrict__ weight,
          const int* __restrict__ in_idx,
          const int* __restrict__ out_idx,
          float* __restrict__ out) {
    const int s = blockIdx.x;                 // segment 0..26
    const unsigned int S = g_segstart[s];
    const unsigned int E = g_segstart[s + 1];

    const int tid = threadIdx.x;
    const int qq = tid >> 2;                  // quad id 0..63
    const int j = tid & 3;                    // float4 quad of the row

    const float4 wj = __ldg(reinterpret_cast<const float4*>(weight) + s * 4 + j);

    for (unsigned int base = S + blockIdx.y * CH; base < E;
         base += gridDim.y * CH) {
        unsigned int m[NS];
        bool vl[NS];
#pragma unroll
        for (int r = 0; r < NS; r++) {
            unsigned int mm = base + r * 64 + qq;
            vl[r] = (mm < E);
            m[r] = vl[r] ? mm : (E - 1);
        }
        int o[NS], ii[NS];
#pragma unroll
        for (int r = 0; r < NS; r++) {
            o[r]  = __ldg(&out_idx[m[r]]);
            ii[r] = __ldg(&in_idx[m[r]]);
        }
        float f[NS];
        unsigned char d[NS];
#pragma unroll
        for (int r = 0; r < NS; r++) {
            f[r] = __ldg(&feats[ii[r]]);
            d[r] = __ldg(&g_counts[o[r]]);
        }
#pragma unroll
        for (int r = 0; r < NS; r++) {
            if (vl[r]) {
                float4 v = make_float4(f[r] * wj.x, f[r] * wj.y,
                                       f[r] * wj.z, f[r] * wj.w);
                float* op = out + (size_t)o[r] * 16 + j * 4;
                if (d[r] == 1) *reinterpret_cast<float4*>(op) = v;
                else           red_add_v4(op, v.x, v.y, v.z, v.w);
            }
        }
    }
}

extern "C" void kernel_launch(void* const* d_in, const int* in_sizes, int n_in,
                              void* d_out, int out_size) {
    const float* feats  = (const float*)d_in[0];
    const float* weight = (const float*)d_in[1];
    const int* in_idx   = (const int*)d_in[2];
    const int* out_idx  = (const int*)d_in[3];
    const int* k_idx    = (const int*)d_in[4];
    float* out = (float*)d_out;

    const int M = in_sizes[2];
    const int n_out = out_size / 16;
    const int Qc = (M + NC - 1) / NC;

    void* counts_ptr = nullptr;
    cudaGetSymbolAddress(&counts_ptr, g_counts);

    const int T = 256;
    cudaMemsetAsync(counts_ptr, 0, (size_t)((n_out + 3) & ~3), 0);
    k_bounds_vec<<<((M + 3) / 4 + T - 1) / T, T>>>(k_idx, M);
    k_count<<<(Qc + T - 1) / T, T>>>(out_idx, M, Qc);
    k_zero_multi<<<((size_t)n_out * 4 + T - 1) / T, T>>>(out, n_out);

    dim3 grid(27, 512);   // x = segment (fastest-varying -> lockstep fractions)
    k_scatter<<<grid, T>>>(feats, weight, in_idx, out_idx, out);
}

// round 16
// speedup vs baseline: 1.1839x; 1.1839x over previous
#include <cuda_runtime.h>
#include <cstdint>

// SimpleSparseConvNet: rulebook sparse conv, Cin=1, Cout=16.
// 3-node pipeline:
//  - memset: zero byte-packed counts.
//  - k_count: byte histogram of out_idx (8 strided address-disjoint streams,
//    value-returning atomics) + inline segment-boundary extraction + INLINE
//    zeroing of deg>=2 rows on the unique 1->2 count transition.
//  - k_scatter: segment-lockstep grid (27, Y); k uniform per block (weight
//    hoisted); deg==1 rows STG.128, deg>=2 rows red.v4 (L2-resident lines
//    thanks to lockstep segment progress).

#define MAX_NOUT (4 * 1024 * 1024)
#define NS 4
#define CH (64 * NS)          // entries per block-chunk in scatter
#define NC 8                  // streams in k_count

__device__ __align__(16) unsigned char g_counts[MAX_NOUT];
__device__ unsigned int g_segstart[32];

__device__ __forceinline__ void red_add_v4(float* addr, float a, float b, float c, float d) {
    asm volatile("red.global.add.v4.f32 [%0], {%1, %2, %3, %4};"
                 :: "l"(addr), "f"(a), "f"(b), "f"(c), "f"(d)
                 : "memory");
}

// ---- K1: histogram + boundaries + transition-triggered row zeroing ----------
__global__ void __launch_bounds__(256)
k_count(const int* __restrict__ out_idx, const int* __restrict__ k_idx,
        float* __restrict__ out, int M, int Q) {
    int q = blockIdx.x * blockDim.x + threadIdx.x;
    if (q >= Q) return;

    const int mLast = q + (NC - 1) * Q;
    const bool vLast = (mLast < M);
    int m[NC];
#pragma unroll
    for (int r = 0; r < NC - 1; r++) m[r] = q + r * Q;
    m[NC - 1] = vLast ? mLast : (M - 1);

    // front-batched loads
    int o[NC], kk[NC], kp[NC];
#pragma unroll
    for (int r = 0; r < NC; r++) {
        o[r]  = __ldg(&out_idx[m[r]]);
        kk[r] = __ldg(&k_idx[m[r]]);
        kp[r] = (m[r] > 0) ? __ldg(&k_idx[m[r] - 1]) : -1;
    }

    // batched value-returning atomics (latency overlapped across streams)
    unsigned int old[NC];
#pragma unroll
    for (int r = 0; r < NC; r++) {
        if (r < NC - 1 || vLast)
            old[r] = atomicAdd(reinterpret_cast<unsigned int*>(g_counts) + (o[r] >> 2),
                               1u << ((o[r] & 3) * 8));
    }

#pragma unroll
    for (int r = 0; r < NC; r++) {
        if (r < NC - 1 || vLast) {
            // unique 1->2 transition: zero the output row inline
            unsigned int oldbyte = (old[r] >> ((o[r] & 3) * 8)) & 0xFFu;
            if (oldbyte == 1u) {
                float4* op = reinterpret_cast<float4*>(out) + (size_t)o[r] * 4;
                const float4 z = make_float4(0.f, 0.f, 0.f, 0.f);
                op[0] = z; op[1] = z; op[2] = z; op[3] = z;
            }
        }
        // boundary writes: idempotent plain stores (safe on clamped duplicate)
        if (kp[r] < kk[r]) {
            for (int t = kp[r] + 1; t <= kk[r]; t++)
                g_segstart[t] = (unsigned int)m[r];
        }
        if (m[r] == M - 1) {
            for (int t = kk[r] + 1; t <= 27; t++)
                g_segstart[t] = (unsigned int)M;
        }
    }
}

// ---- K2: segment-lockstep scatter --------------------------------------------
__global__ void __launch_bounds__(256)
k_scatter(const float* __restrict__ feats,
          const float* __restrict__ weight,
          const int* __restrict__ in_idx,
          const int* __restrict__ out_idx,
          float* __restrict__ out) {
    const int s = blockIdx.x;                 // segment 0..26
    const unsigned int S = g_segstart[s];
    const unsigned int E = g_segstart[s + 1];

    const int tid = threadIdx.x;
    const int qq = tid >> 2;                  // quad id 0..63
    const int j = tid & 3;                    // float4 quad of the row

    const float4 wj = __ldg(reinterpret_cast<const float4*>(weight) + s * 4 + j);

    for (unsigned int base = S + blockIdx.y * CH; base < E;
         base += gridDim.y * CH) {
        unsigned int m[NS];
        bool vl[NS];
#pragma unroll
        for (int r = 0; r < NS; r++) {
            unsigned int mm = base + r * 64 + qq;
            vl[r] = (mm < E);
            m[r] = vl[r] ? mm : (E - 1);
        }
        int o[NS], ii[NS];
#pragma unroll
        for (int r = 0; r < NS; r++) {
            o[r]  = __ldg(&out_idx[m[r]]);
            ii[r] = __ldg(&in_idx[m[r]]);
        }
        float f[NS];
        unsigned char d[NS];
#pragma unroll
        for (int r = 0; r < NS; r++) {
            f[r] = __ldg(&feats[ii[r]]);
            d[r] = __ldg(&g_counts[o[r]]);
        }
#pragma unroll
        for (int r = 0; r < NS; r++) {
            if (vl[r]) {
                float4 v = make_float4(f[r] * wj.x, f[r] * wj.y,
                                       f[r] * wj.z, f[r] * wj.w);
                float* op = out + (size_t)o[r] * 16 + j * 4;
                if (d[r] == 1) *reinterpret_cast<float4*>(op) = v;
                else           red_add_v4(op, v.x, v.y, v.z, v.w);
            }
        }
    }
}

extern "C" void kernel_launch(void* const* d_in, const int* in_sizes, int n_in,
                              void* d_out, int out_size) {
    const float* feats  = (const float*)d_in[0];
    const float* weight = (const float*)d_in[1];
    const int* in_idx   = (const int*)d_in[2];
    const int* out_idx  = (const int*)d_in[3];
    const int* k_idx    = (const int*)d_in[4];
    float* out = (float*)d_out;

    const int M = in_sizes[2];
    const int n_out = out_size / 16;
    const int Qc = (M + NC - 1) / NC;

    void* counts_ptr = nullptr;
    cudaGetSymbolAddress(&counts_ptr, g_counts);

    const int T = 256;
    cudaMemsetAsync(counts_ptr, 0, (size_t)((n_out + 3) & ~3), 0);
    k_count<<<(Qc + T - 1) / T, T>>>(out_idx, k_idx, out, M, Qc);

    dim3 grid(27, 512);   // x = segment (fastest-varying -> lockstep fractions)
    k_scatter<<<grid, T>>>(feats, weight, in_idx, out_idx, out);
}